// round 17
// baseline (speedup 1.0000x reference)
#include <cuda_runtime.h>
#include <cuda_fp16.h>
#include <cstdint>

typedef unsigned int u32;

#define BB  8
#define SS  1024
#define DD  1024
#define HH  16
#define DKK 64
#define MTOT 8192
#define NEL  8388608
#define WEL  1048576
#define AEL  134217728ULL

// ---------------------------------------------------------------------------
// Scratch (__device__ globals; allocation-free rule)
// ---------------------------------------------------------------------------
__device__ __half gQih[NEL], gKih[NEL], gVih[NEL];
__device__ __half gWqh[WEL], gWkh[WEL], gWvh[WEL], gWoh[WEL];
__device__ __half gqh[NEL], gkh[NEL], gvh[NEL];
__device__ __half gattnh[AEL];
__device__ __half gctxh[NEL];

// ---------------------------------------------------------------------------
// Baseline-ISA tensor helpers (compile under compute_103)
// ---------------------------------------------------------------------------
__device__ __forceinline__ u32 smem_u32(const void* p) {
    u32 a;
    asm("{ .reg .u64 t; cvta.to.shared.u64 t, %1; cvt.u32.u64 %0, t; }" : "=r"(a) : "l"(p));
    return a;
}
__device__ __forceinline__ void ldsm4(u32& r0, u32& r1, u32& r2, u32& r3, u32 a) {
    asm volatile("ldmatrix.sync.aligned.m8n8.x4.shared.b16 {%0,%1,%2,%3}, [%4];"
                 : "=r"(r0), "=r"(r1), "=r"(r2), "=r"(r3) : "r"(a));
}
__device__ __forceinline__ void ldsm4t(u32& r0, u32& r1, u32& r2, u32& r3, u32 a) {
    asm volatile("ldmatrix.sync.aligned.m8n8.x4.trans.shared.b16 {%0,%1,%2,%3}, [%4];"
                 : "=r"(r0), "=r"(r1), "=r"(r2), "=r"(r3) : "r"(a));
}
__device__ __forceinline__ void mma_f16(float* c, const u32* a, u32 b0, u32 b1) {
    asm volatile(
        "mma.sync.aligned.m16n8k16.row.col.f32.f16.f16.f32 "
        "{%0,%1,%2,%3}, {%4,%5,%6,%7}, {%8,%9}, {%0,%1,%2,%3};"
        : "+f"(c[0]), "+f"(c[1]), "+f"(c[2]), "+f"(c[3])
        : "r"(a[0]), "r"(a[1]), "r"(a[2]), "r"(a[3]), "r"(b0), "r"(b1));
}
__device__ __forceinline__ void cp16(u32 dst, const void* src) {
    asm volatile("cp.async.cg.shared.global [%0], [%1], 16;" :: "r"(dst), "l"(src));
}
#define CP_COMMIT() asm volatile("cp.async.commit_group;" ::: "memory")
#define CP_WAIT0()  asm volatile("cp.async.wait_group 0;" ::: "memory")
#define CP_WAIT1()  asm volatile("cp.async.wait_group 1;" ::: "memory")

// ---------------------------------------------------------------------------
// fp32 -> fp16 converts: one launch for QKV (z=3), one for weights (z=4)
// ---------------------------------------------------------------------------
__global__ __launch_bounds__(256) void conv3_kernel(const float* __restrict__ x0,
                                                    const float* __restrict__ x1,
                                                    const float* __restrict__ x2,
                                                    __half* __restrict__ o0,
                                                    __half* __restrict__ o1,
                                                    __half* __restrict__ o2) {
    const float* xs[3] = {x0, x1, x2};
    __half* os[3] = {o0, o1, o2};
    const float* x = xs[blockIdx.y];
    __half* hi = os[blockIdx.y];
    const int i = (blockIdx.x * 256 + threadIdx.x) * 4;
    float4 v = *(const float4*)(x + i);
    __half2 H0; H0.x = __float2half_rn(v.x); H0.y = __float2half_rn(v.y);
    __half2 H1; H1.x = __float2half_rn(v.z); H1.y = __float2half_rn(v.w);
    *(__half2*)(hi + i)     = H0;
    *(__half2*)(hi + i + 2) = H1;
}

__global__ __launch_bounds__(256) void conv4_kernel(const float* __restrict__ x0,
                                                    const float* __restrict__ x1,
                                                    const float* __restrict__ x2,
                                                    const float* __restrict__ x3,
                                                    __half* __restrict__ o0,
                                                    __half* __restrict__ o1,
                                                    __half* __restrict__ o2,
                                                    __half* __restrict__ o3) {
    const float* xs[4] = {x0, x1, x2, x3};
    __half* os[4] = {o0, o1, o2, o3};
    const float* x = xs[blockIdx.y];
    __half* hi = os[blockIdx.y];
    const int i = (blockIdx.x * 256 + threadIdx.x) * 4;
    float4 v = *(const float4*)(x + i);
    __half2 H0; H0.x = __float2half_rn(v.x); H0.y = __float2half_rn(v.y);
    __half2 H1; H1.x = __float2half_rn(v.z); H1.y = __float2half_rn(v.w);
    *(__half2*)(hi + i)     = H0;
    *(__half2*)(hi + i + 2) = H1;
}

// ---------------------------------------------------------------------------
// 1-pass GEMM core (128x128 tile, BK=32, double-buffered, 8 warps 64x32)
// ---------------------------------------------------------------------------
#define GST    80                 // smem row stride bytes (40 fp16)
#define GMAT   (128 * GST)        // 10240
#define GSTAGE1 (2 * GMAT)        // [Ah][Bh]
#define GEMM1_SMEM (2 * GSTAGE1)  // 40960

// Fused projections: grid (8, 64, 3); z selects X/W/bias/out; fp16 out [B,H,S,DK]
__global__ __launch_bounds__(256) void proj_mma(
    const __half* __restrict__ A0, const __half* __restrict__ A1, const __half* __restrict__ A2,
    const __half* __restrict__ B0, const __half* __restrict__ B1, const __half* __restrict__ B2,
    const float* __restrict__ b0p, const float* __restrict__ b1p, const float* __restrict__ b2p,
    __half* __restrict__ O0, __half* __restrict__ O1, __half* __restrict__ O2) {
    extern __shared__ char smarr[];
    const u32 sb = smem_u32(smarr);
    const int tid = threadIdx.x, lane = tid & 31, wid = tid >> 5;
    const int wm = wid & 1, wn = wid >> 1;
    const int m0 = blockIdx.y * 128, n0 = blockIdx.x * 128;

    const __half* As[3] = {A0, A1, A2};
    const __half* Bs[3] = {B0, B1, B2};
    const float* bs[3] = {b0p, b1p, b2p};
    __half* Os[3] = {O0, O1, O2};
    const int z = blockIdx.z;
    const __half* Ahg = As[z];
    const __half* Bhg = Bs[z];
    const float* bias = bs[z];
    __half* o_hi = Os[z];

    float acc[4][4][4];
#pragma unroll
    for (int a = 0; a < 4; ++a)
#pragma unroll
        for (int b = 0; b < 4; ++b)
#pragma unroll
            for (int c = 0; c < 4; ++c) acc[a][b][c] = 0.f;

    const __half* gsrc[2] = {Ahg + (size_t)m0 * DD, Bhg + (size_t)n0 * DD};

    auto LOAD = [&](int kt, int buf) {
        const int ko = kt * 32;
#pragma unroll
        for (int mat = 0; mat < 2; ++mat)
#pragma unroll
            for (int i = 0; i < 2; ++i) {
                const int ch = tid + i * 256;
                const int row = ch >> 2, c = ch & 3;
                cp16(sb + buf * GSTAGE1 + mat * GMAT + row * GST + c * 16,
                     gsrc[mat] + (size_t)row * DD + ko + c * 8);
            }
    };

    auto COMP = [&](int buf) {
        const u32 st = sb + buf * GSTAGE1;
#pragma unroll
        for (int s = 0; s < 2; ++s) {
            u32 ah[4][4];
#pragma unroll
            for (int mt = 0; mt < 4; ++mt) {
                const int row = wm * 64 + mt * 16 + (lane & 15);
                const int colb = (s * 16 + (lane >> 4) * 8) * 2;
                ldsm4(ah[mt][0], ah[mt][1], ah[mt][2], ah[mt][3], st + row * GST + colb);
            }
            u32 bh[2][4];
#pragma unroll
            for (int bt = 0; bt < 2; ++bt) {
                const int row = wn * 32 + bt * 16 + ((lane >> 4) & 1) * 8 + (lane & 7);
                const int colb = (s * 16 + ((lane >> 3) & 1) * 8) * 2;
                ldsm4(bh[bt][0], bh[bt][1], bh[bt][2], bh[bt][3],
                      st + GMAT + row * GST + colb);
            }
#pragma unroll
            for (int mt = 0; mt < 4; ++mt)
#pragma unroll
                for (int bt = 0; bt < 2; ++bt)
#pragma unroll
                    for (int j = 0; j < 2; ++j)
                        mma_f16(acc[mt][bt * 2 + j], ah[mt], bh[bt][2 * j], bh[bt][2 * j + 1]);
        }
    };

    LOAD(0, 0); CP_COMMIT();
    for (int kt = 0; kt < 32; ++kt) {
        const int buf = kt & 1;
        if (kt + 1 < 32) { LOAD(kt + 1, buf ^ 1); CP_COMMIT(); CP_WAIT1(); }
        else             { CP_WAIT0(); }
        __syncthreads();
        COMP(buf);
        __syncthreads();
    }

    const int r0 = lane >> 2, cp = (lane & 3) * 2;
#pragma unroll
    for (int mt = 0; mt < 4; ++mt)
#pragma unroll
        for (int i = 0; i < 2; ++i) {
            const int m = m0 + wm * 64 + mt * 16 + r0 + i * 8;
#pragma unroll
            for (int nt = 0; nt < 4; ++nt) {
                const int n = n0 + wn * 32 + nt * 8 + cp;
                float v0 = acc[mt][nt][i * 2 + 0] + __ldg(&bias[n]);
                float v1 = acc[mt][nt][i * 2 + 1] + __ldg(&bias[n + 1]);
                const int bI = m >> 10, s = m & 1023;
                const int h = n >> 6, d = n & 63;
                const size_t o = ((size_t)(bI * HH + h) * SS + s) * DKK + d;
                __half2 hh;
                hh.x = __float2half_rn(v0); hh.y = __float2half_rn(v1);
                *(__half2*)&o_hi[o] = hh;
            }
        }
}

// Out-projection GEMM: fp32 out + bias + Qres
__global__ __launch_bounds__(256) void outproj_mma(
    const __half* __restrict__ Ahg, const __half* __restrict__ Bhg,
    const float* __restrict__ bias, const float* __restrict__ Qres,
    float* __restrict__ o_f) {
    extern __shared__ char smarr[];
    const u32 sb = smem_u32(smarr);
    const int tid = threadIdx.x, lane = tid & 31, wid = tid >> 5;
    const int wm = wid & 1, wn = wid >> 1;
    const int m0 = blockIdx.y * 128, n0 = blockIdx.x * 128;

    float acc[4][4][4];
#pragma unroll
    for (int a = 0; a < 4; ++a)
#pragma unroll
        for (int b = 0; b < 4; ++b)
#pragma unroll
            for (int c = 0; c < 4; ++c) acc[a][b][c] = 0.f;

    const __half* gsrc[2] = {Ahg + (size_t)m0 * DD, Bhg + (size_t)n0 * DD};

    auto LOAD = [&](int kt, int buf) {
        const int ko = kt * 32;
#pragma unroll
        for (int mat = 0; mat < 2; ++mat)
#pragma unroll
            for (int i = 0; i < 2; ++i) {
                const int ch = tid + i * 256;
                const int row = ch >> 2, c = ch & 3;
                cp16(sb + buf * GSTAGE1 + mat * GMAT + row * GST + c * 16,
                     gsrc[mat] + (size_t)row * DD + ko + c * 8);
            }
    };

    auto COMP = [&](int buf) {
        const u32 st = sb + buf * GSTAGE1;
#pragma unroll
        for (int s = 0; s < 2; ++s) {
            u32 ah[4][4];
#pragma unroll
            for (int mt = 0; mt < 4; ++mt) {
                const int row = wm * 64 + mt * 16 + (lane & 15);
                const int colb = (s * 16 + (lane >> 4) * 8) * 2;
                ldsm4(ah[mt][0], ah[mt][1], ah[mt][2], ah[mt][3], st + row * GST + colb);
            }
            u32 bh[2][4];
#pragma unroll
            for (int bt = 0; bt < 2; ++bt) {
                const int row = wn * 32 + bt * 16 + ((lane >> 4) & 1) * 8 + (lane & 7);
                const int colb = (s * 16 + ((lane >> 3) & 1) * 8) * 2;
                ldsm4(bh[bt][0], bh[bt][1], bh[bt][2], bh[bt][3],
                      st + GMAT + row * GST + colb);
            }
#pragma unroll
            for (int mt = 0; mt < 4; ++mt)
#pragma unroll
                for (int bt = 0; bt < 2; ++bt)
#pragma unroll
                    for (int j = 0; j < 2; ++j)
                        mma_f16(acc[mt][bt * 2 + j], ah[mt], bh[bt][2 * j], bh[bt][2 * j + 1]);
        }
    };

    LOAD(0, 0); CP_COMMIT();
    for (int kt = 0; kt < 32; ++kt) {
        const int buf = kt & 1;
        if (kt + 1 < 32) { LOAD(kt + 1, buf ^ 1); CP_COMMIT(); CP_WAIT1(); }
        else             { CP_WAIT0(); }
        __syncthreads();
        COMP(buf);
        __syncthreads();
    }

    const int r0 = lane >> 2, cp = (lane & 3) * 2;
#pragma unroll
    for (int mt = 0; mt < 4; ++mt)
#pragma unroll
        for (int i = 0; i < 2; ++i) {
            const int m = m0 + wm * 64 + mt * 16 + r0 + i * 8;
#pragma unroll
            for (int nt = 0; nt < 4; ++nt) {
                const int n = n0 + wn * 32 + nt * 8 + cp;
                float v0 = acc[mt][nt][i * 2 + 0] + __ldg(&bias[n]);
                float v1 = acc[mt][nt][i * 2 + 1] + __ldg(&bias[n + 1]);
                const size_t o = (size_t)m * DD + n;
                float2 qv = *(const float2*)&Qres[o];
                float2 val; val.x = v0 + qv.x; val.y = v1 + qv.y;
                *(float2*)&o_f[o] = val;
            }
        }
}

// ---------------------------------------------------------------------------
// scores via mma.sync (1-pass): per (b,h) 128x128 tile, K=64 single stage
//   S = qh @ kh^T
// ---------------------------------------------------------------------------
#define SSTR 144
#define SMAT (128 * SSTR)       // 18432
#define SC_SMEM (2 * SMAT)      // 36864

__global__ __launch_bounds__(256) void scores_mma(
    const __half* __restrict__ qh, const __half* __restrict__ kh,
    const unsigned char* __restrict__ mask, float* __restrict__ scores) {
    extern __shared__ char smarr[];
    const u32 sb = smem_u32(smarr);
    const int tid = threadIdx.x, lane = tid & 31, wid = tid >> 5;
    const int wm = wid & 1, wn = wid >> 1;
    const int bh = blockIdx.z;
    const int m0 = blockIdx.y * 128, n0 = blockIdx.x * 128;

    const __half* gsrc[2] = {
        qh + ((size_t)bh * SS + m0) * DKK,
        kh + ((size_t)bh * SS + n0) * DKK};
#pragma unroll
    for (int mat = 0; mat < 2; ++mat)
#pragma unroll
        for (int i = 0; i < 4; ++i) {
            const int ch = tid + i * 256;
            const int row = ch >> 3, c = ch & 7;
            cp16(sb + mat * SMAT + row * SSTR + c * 16,
                 gsrc[mat] + (size_t)row * DKK + c * 8);
        }
    CP_COMMIT(); CP_WAIT0();
    __syncthreads();

    float acc[4][4][4];
#pragma unroll
    for (int a = 0; a < 4; ++a)
#pragma unroll
        for (int b = 0; b < 4; ++b)
#pragma unroll
            for (int c = 0; c < 4; ++c) acc[a][b][c] = 0.f;

#pragma unroll
    for (int s = 0; s < 4; ++s) {
        u32 ah[4][4];
#pragma unroll
        for (int mt = 0; mt < 4; ++mt) {
            const int row = wm * 64 + mt * 16 + (lane & 15);
            const int colb = (s * 16 + (lane >> 4) * 8) * 2;
            ldsm4(ah[mt][0], ah[mt][1], ah[mt][2], ah[mt][3], sb + row * SSTR + colb);
        }
        u32 bh_[2][4];
#pragma unroll
        for (int bt = 0; bt < 2; ++bt) {
            const int row = wn * 32 + bt * 16 + ((lane >> 4) & 1) * 8 + (lane & 7);
            const int colb = (s * 16 + ((lane >> 3) & 1) * 8) * 2;
            ldsm4(bh_[bt][0], bh_[bt][1], bh_[bt][2], bh_[bt][3],
                  sb + SMAT + row * SSTR + colb);
        }
#pragma unroll
        for (int mt = 0; mt < 4; ++mt)
#pragma unroll
            for (int bt = 0; bt < 2; ++bt)
#pragma unroll
                for (int j = 0; j < 2; ++j)
                    mma_f16(acc[mt][bt * 2 + j], ah[mt], bh_[bt][2 * j], bh_[bt][2 * j + 1]);
    }

    const int bI = bh >> 4;
    float* srow = scores + (size_t)bh * SS * SS;
    const unsigned char* mrow = mask + (size_t)bI * SS * SS;
    const int r0 = lane >> 2, cp = (lane & 3) * 2;
#pragma unroll
    for (int mt = 0; mt < 4; ++mt)
#pragma unroll
        for (int i = 0; i < 2; ++i) {
            const int m = m0 + wm * 64 + mt * 16 + r0 + i * 8;
#pragma unroll
            for (int nt = 0; nt < 4; ++nt) {
                const int n = n0 + wn * 32 + nt * 8 + cp;
                float v0 = acc[mt][nt][i * 2 + 0] * 0.125f;
                float v1 = acc[mt][nt][i * 2 + 1] * 0.125f;
                uchar2 mk = *(const uchar2*)&mrow[(size_t)m * SS + n];
                if (mk.x) v0 = -1e9f;
                if (mk.y) v1 = -1e9f;
                float2 val; val.x = v0; val.y = v1;
                *(float2*)&srow[(size_t)m * SS + n] = val;
            }
        }
}

// ---------------------------------------------------------------------------
// softmax: one WARP per 1024-float row; shfl-only reductions, MLP=8
// ---------------------------------------------------------------------------
__global__ __launch_bounds__(256) void softmax_kernel(const float* __restrict__ scores,
                                                      float* __restrict__ attn,
                                                      __half* __restrict__ ahi) {
    const int w = threadIdx.x >> 5, lane = threadIdx.x & 31;
    const size_t row = (size_t)blockIdx.x * 8 + w;
    const float4* src = (const float4*)(scores + row * SS);

    float4 x[8];
#pragma unroll
    for (int i = 0; i < 8; ++i) x[i] = src[lane + 32 * i];

    float mx = -1e30f;
#pragma unroll
    for (int i = 0; i < 8; ++i)
        mx = fmaxf(mx, fmaxf(fmaxf(x[i].x, x[i].y), fmaxf(x[i].z, x[i].w)));
#pragma unroll
    for (int o = 16; o; o >>= 1) mx = fmaxf(mx, __shfl_xor_sync(0xffffffffu, mx, o));

    float s = 0.f;
#pragma unroll
    for (int i = 0; i < 8; ++i) {
        x[i].x = __expf(x[i].x - mx); x[i].y = __expf(x[i].y - mx);
        x[i].z = __expf(x[i].z - mx); x[i].w = __expf(x[i].w - mx);
        s += (x[i].x + x[i].y) + (x[i].z + x[i].w);
    }
#pragma unroll
    for (int o = 16; o; o >>= 1) s += __shfl_xor_sync(0xffffffffu, s, o);
    const float inv = 1.0f / s;

    float4* adst = (float4*)(attn + row * SS);
    __half* hdst = ahi + row * SS;
#pragma unroll
    for (int i = 0; i < 8; ++i) {
        float4 r;
        r.x = x[i].x * inv; r.y = x[i].y * inv;
        r.z = x[i].z * inv; r.w = x[i].w * inv;
        adst[lane + 32 * i] = r;
        __half2 H0; H0.x = __float2half_rn(r.x); H0.y = __float2half_rn(r.y);
        __half2 H1; H1.x = __float2half_rn(r.z); H1.y = __float2half_rn(r.w);
        const int c = (lane + 32 * i) * 4;
        *(__half2*)(hdst + c)     = H0;
        *(__half2*)(hdst + c + 2) = H1;
    }
}

// ---------------------------------------------------------------------------
// context (1-pass): ctx = attn_h @ Vh, writes ctx hi only
// ---------------------------------------------------------------------------
#define CAMAT  (128 * 80)                 // 10240
#define CVMAT  (32 * 144)                 // 4608
#define CSTAGE (CAMAT + CVMAT)            // 14848: [Ah][Vh]
#define CTX_SMEM (2 * CSTAGE)             // 29696

__global__ __launch_bounds__(256) void context_mma(
    const __half* __restrict__ ahg, const __half* __restrict__ vhg,
    __half* __restrict__ ctxh) {
    extern __shared__ char smarr[];
    const u32 sb = smem_u32(smarr);
    const int tid = threadIdx.x, lane = tid & 31, wid = tid >> 5;
    const int wm = wid >> 1, wn = wid & 1;
    const int bh = blockIdx.y;
    const int m0 = blockIdx.x * 128;

    const __half* asrc = ahg + ((size_t)bh * SS + m0) * SS;
    const __half* vsrc = vhg + (size_t)bh * SS * DKK;

    float acc[2][4][4];
#pragma unroll
    for (int a = 0; a < 2; ++a)
#pragma unroll
        for (int b = 0; b < 4; ++b)
#pragma unroll
            for (int c = 0; c < 4; ++c) acc[a][b][c] = 0.f;

    auto LOAD = [&](int kt, int buf) {
        const int ko = kt * 32;
#pragma unroll
        for (int i = 0; i < 2; ++i) {
            const int ch = tid + i * 256;
            const int row = ch >> 2, c = ch & 3;
            cp16(sb + buf * CSTAGE + row * 80 + c * 16,
                 asrc + (size_t)row * SS + ko + c * 8);
        }
        const int vr = tid >> 3, vc = tid & 7;
        cp16(sb + buf * CSTAGE + CAMAT + vr * 144 + vc * 16,
             vsrc + (size_t)(ko + vr) * DKK + vc * 8);
    };

    auto COMP = [&](int buf) {
        const u32 st = sb + buf * CSTAGE;
#pragma unroll
        for (int s = 0; s < 2; ++s) {
            u32 ah[2][4];
#pragma unroll
            for (int mt = 0; mt < 2; ++mt) {
                const int row = wm * 32 + mt * 16 + (lane & 15);
                const int colb = (s * 16 + (lane >> 4) * 8) * 2;
                ldsm4(ah[mt][0], ah[mt][1], ah[mt][2], ah[mt][3], st + row * 80 + colb);
            }
            u32 bh_[2][4];
#pragma unroll
            for (int bt = 0; bt < 2; ++bt) {
                const int rowk = s * 16 + (lane & 7) + ((lane >> 3) & 1) * 8;
                const int coln = wn * 32 + bt * 16 + ((lane >> 4) & 1) * 8;
                ldsm4t(bh_[bt][0], bh_[bt][1], bh_[bt][2], bh_[bt][3],
                       st + CAMAT + rowk * 144 + coln * 2);
            }
#pragma unroll
            for (int mt = 0; mt < 2; ++mt)
#pragma unroll
                for (int bt = 0; bt < 2; ++bt)
#pragma unroll
                    for (int j = 0; j < 2; ++j)
                        mma_f16(acc[mt][bt * 2 + j], ah[mt], bh_[bt][2 * j], bh_[bt][2 * j + 1]);
        }
    };

    LOAD(0, 0); CP_COMMIT();
    for (int kt = 0; kt < 32; ++kt) {
        const int buf = kt & 1;
        if (kt + 1 < 32) { LOAD(kt + 1, buf ^ 1); CP_COMMIT(); CP_WAIT1(); }
        else             { CP_WAIT0(); }
        __syncthreads();
        COMP(buf);
        __syncthreads();
    }

    const int bI = bh >> 4, h = bh & 15;
    const int r0 = lane >> 2, cp = (lane & 3) * 2;
#pragma unroll
    for (int mt = 0; mt < 2; ++mt)
#pragma unroll
        for (int i = 0; i < 2; ++i) {
            const int m = m0 + wm * 32 + mt * 16 + r0 + i * 8;
#pragma unroll
            for (int nt = 0; nt < 4; ++nt) {
                const int n = wn * 32 + nt * 8 + cp;
                __half2 hh;
                hh.x = __float2half_rn(acc[mt][nt][i * 2 + 0]);
                hh.y = __float2half_rn(acc[mt][nt][i * 2 + 1]);
                const size_t o = ((size_t)bI * SS + m) * DD + h * DKK + n;
                *(__half2*)&ctxh[o] = hh;
            }
        }
}

// ---------------------------------------------------------------------------
// launch
// ---------------------------------------------------------------------------
extern "C" void kernel_launch(void* const* d_in, const int* in_sizes, int n_in,
                              void* d_out, int out_size) {
    const float* Q  = (const float*)d_in[0];
    const float* K  = (const float*)d_in[1];
    const float* V  = (const float*)d_in[2];
    const unsigned char* mask = (const unsigned char*)d_in[3];
    const float* Wq = (const float*)d_in[4];
    const float* bq = (const float*)d_in[5];
    const float* Wk = (const float*)d_in[6];
    const float* bk = (const float*)d_in[7];
    const float* Wv = (const float*)d_in[8];
    const float* bv = (const float*)d_in[9];
    const float* Wo = (const float*)d_in[10];
    const float* bo = (const float*)d_in[11];

    float* out    = (float*)d_out;
    float* attn   = out + (size_t)BB * SS * DD;
    float* scores = attn + (size_t)BB * HH * SS * SS;

    __half *pQih, *pKih, *pVih;
    __half *pWqh, *pWkh, *pWvh, *pWoh;
    __half *pqh, *pkh, *pvh, *pah, *pctxh;
    cudaGetSymbolAddress((void**)&pQih, gQih);
    cudaGetSymbolAddress((void**)&pKih, gKih);
    cudaGetSymbolAddress((void**)&pVih, gVih);
    cudaGetSymbolAddress((void**)&pWqh, gWqh); cudaGetSymbolAddress((void**)&pWkh, gWkh);
    cudaGetSymbolAddress((void**)&pWvh, gWvh); cudaGetSymbolAddress((void**)&pWoh, gWoh);
    cudaGetSymbolAddress((void**)&pqh, gqh);   cudaGetSymbolAddress((void**)&pkh, gkh);
    cudaGetSymbolAddress((void**)&pvh, gvh);
    cudaGetSymbolAddress((void**)&pah, gattnh);
    cudaGetSymbolAddress((void**)&pctxh, gctxh);

    static int initd = 0;
    if (!initd) {
        cudaFuncSetAttribute(proj_mma, cudaFuncAttributeMaxDynamicSharedMemorySize, GEMM1_SMEM);
        cudaFuncSetAttribute(outproj_mma, cudaFuncAttributeMaxDynamicSharedMemorySize, GEMM1_SMEM);
        cudaFuncSetAttribute(scores_mma, cudaFuncAttributeMaxDynamicSharedMemorySize, SC_SMEM);
        cudaFuncSetAttribute(context_mma, cudaFuncAttributeMaxDynamicSharedMemorySize, CTX_SMEM);
        initd = 1;
    }

    conv3_kernel<<<dim3(NEL / 1024, 3), 256>>>(Q, K, V, pQih, pKih, pVih);
    conv4_kernel<<<dim3(WEL / 1024, 4), 256>>>(Wq, Wk, Wv, Wo, pWqh, pWkh, pWvh, pWoh);

    const dim3 projGrid(DD / 128, MTOT / 128, 3);       // (8, 64, 3)
    proj_mma<<<projGrid, 256, GEMM1_SMEM>>>(pQih, pKih, pVih,
                                            pWqh, pWkh, pWvh,
                                            bq, bk, bv,
                                            pqh, pkh, pvh);

    const dim3 scoreGrid(SS / 128, SS / 128, BB * HH);  // (8, 8, 128)
    scores_mma<<<scoreGrid, 256, SC_SMEM>>>(pqh, pkh, mask, scores);

    softmax_kernel<<<BB * HH * SS / 8, 256>>>(scores, attn, pah);

    const dim3 ctxGrid(SS / 128, BB * HH);              // (8, 128)
    context_mma<<<ctxGrid, 256, CTX_SMEM>>>(pah, pvh, pctxh);

    const dim3 oGrid(DD / 128, MTOT / 128);             // (8, 64)
    outproj_mma<<<oGrid, 256, GEMM1_SMEM>>>(pctxh, pWoh, bo, Q, out);
}